// round 15
// baseline (speedup 1.0000x reference)
#include <cuda_runtime.h>
#include <math.h>

// Problem constants (B=1, C_IN=3, H=W=96, FEAT=64, GDIM=8, BLOCK=16)
#define Hh   96
#define Ww   96
#define HW   (96 * 96)
#define GD   8
#define FEAT 64
#define CIN  3

#define NB   144   // blocks: <=148 SMs, 1 block/SM -> all co-resident in wave 1
#define NT   512   // threads/block

#define LN255 5.5412635f   // ln(255); alpha >= 1/255  <=>  sigma <= ln(255)

// 32-byte gaussian record (tile bounds proven redundant: radius >= 2 always,
// and any sigma-gate survivor has |d| <= 1.665 < radius => tile test passes).
struct __align__(16) GParam {
    float cx, cy, ca, cb, cc, r0, r1, r2;
};

__device__ GParam g_gauss[HW];   // 288 KB scratch (device global: no allocations)
__device__ int    g_arrive = 0;  // grid barrier counters (self-resetting per launch)
__device__ int    g_depart = 0;

// ---------------------------------------------------------------------------
// Fused kernel (R12 skeleton): stage weights -> collapse (2 threads/entry,
// shfl-combined) -> conv -> activations -> grid barrier -> STAGE the block's
// 6x96 gaussian slab into shared -> rasterize from LDS over the exact 5x5
// window.
// ---------------------------------------------------------------------------
__global__ __launch_bounds__(NT)
void fused_kernel(const float* __restrict__ inp,
                  const float* __restrict__ w_enc,
                  const float* __restrict__ b_enc,
                  const float* __restrict__ w_head,
                  const float* __restrict__ b_head,
                  float* __restrict__ out)
{
    __shared__ float  s_we[FEAT * 27];   // w_enc  [c*27 + k]
    __shared__ float  s_wh[FEAT * GD];   // w_head TRANSPOSED [c*8 + o]
    __shared__ float  s_be[FEAT];
    __shared__ float  s_bh[GD];
    __shared__ float  sw[GD * 27];       // collapsed weights [o*27 + k]
    __shared__ float  sb[GD];
    __shared__ float  spred[64 * GD];    // per-gaussian raw preds [gi*8 + o]
    __shared__ GParam s_g[6 * Ww];       // post-barrier gaussian slab (18.4 KB)

    const int tid = threadIdx.x;
    const int bid = blockIdx.x;
    const int p0  = bid * 64;            // first pixel of this block

    // ---- stage raw weights to shared ---------------------------------------
    for (int t = tid; t < FEAT * 27; t += NT) s_we[t] = __ldg(&w_enc[t]);
    {   // transpose w_head into [c][o]  (tid < 512 == FEAT*GD)
        const int c = tid >> 3, o = tid & 7;
        s_wh[c * GD + o] = __ldg(&w_head[o * FEAT + c]);
    }
    if (tid < FEAT) s_be[tid] = __ldg(&b_enc[tid]);
    if (tid < GD)   s_bh[tid] = __ldg(&b_head[tid]);
    __syncthreads();

    // ---- collapse: 2 threads per entry (32 channels each), shfl-combined ---
    if (tid < 448) {
        const int e    = tid >> 1;       // entry [0,224): 216 weights + 8 biases
        const int half = tid & 1;
        const int cb   = half * 32;
        float a0 = 0.f, a1 = 0.f, a2 = 0.f, a3 = 0.f;
        if (e < GD * 27) {
            const int o = e / 27, k = e % 27;
            #pragma unroll
            for (int c = cb; c < cb + 32; c += 4) {
                a0 += s_wh[(c    ) * GD + o] * s_we[(c    ) * 27 + k];
                a1 += s_wh[(c + 1) * GD + o] * s_we[(c + 1) * 27 + k];
                a2 += s_wh[(c + 2) * GD + o] * s_we[(c + 2) * 27 + k];
                a3 += s_wh[(c + 3) * GD + o] * s_we[(c + 3) * 27 + k];
            }
        } else {
            const int o = e - GD * 27;
            #pragma unroll
            for (int c = cb; c < cb + 32; c += 4) {
                a0 += s_wh[(c    ) * GD + o] * s_be[c    ];
                a1 += s_wh[(c + 1) * GD + o] * s_be[c + 1];
                a2 += s_wh[(c + 2) * GD + o] * s_be[c + 2];
                a3 += s_wh[(c + 3) * GD + o] * s_be[c + 3];
            }
        }
        float part = (a0 + a1) + (a2 + a3);
        part += __shfl_xor_sync(0xFFFFFFFFu, part, 1);   // pair lanes adjacent
        if (half == 0) {
            if (e < GD * 27) sw[e] = part;
            else             sb[e - GD * 27] = part + s_bh[e - GD * 27];
        }
    }
    __syncthreads();

    // ---- phase A1: conv, 8 threads per gaussian (27 MACs each) -------------
    {
        const int gi = tid >> 3;          // gaussian within block [0,64)
        const int o  = tid & 7;           // output channel
        const int p  = p0 + gi;
        const int w  = p % Ww;
        const int h  = p / Ww;

        float acc = sb[o];
        #pragma unroll
        for (int ci = 0; ci < CIN; ++ci) {
            #pragma unroll
            for (int ky = 0; ky < 3; ++ky) {
                const int y = h + ky - 1;
                #pragma unroll
                for (int kx = 0; kx < 3; ++kx) {
                    const int x = w + kx - 1;
                    float v = 0.f;
                    if (y >= 0 && y < Hh && x >= 0 && x < Ww)
                        v = __ldg(&inp[ci * HW + y * Ww + x]);
                    acc += v * sw[o * 27 + ci * 9 + ky * 3 + kx];
                }
            }
        }
        spred[gi * GD + o] = acc;
    }
    __syncthreads();

    // ---- phase A2: activation/covariance chain, 1 thread per gaussian ------
    if (tid < 64) {
        const int p = p0 + tid;
        const int w = p % Ww;
        const int h = p / Ww;
        float pred[GD];
        #pragma unroll
        for (int o = 0; o < GD; ++o) pred[o] = spred[tid * GD + o];

        const float theta = (1.f / (1.f + __expf(-pred[3]))) * 6.283185307179586f;
        const float s0 = (1.f / (1.f + __expf(-pred[4]))) * 0.5f + 1e-6f;
        const float s1 = (1.f / (1.f + __expf(-pred[5]))) * 0.5f + 1e-6f;
        const float off0 = tanhf(pred[6]);
        const float off1 = tanhf(pred[7]);

        const float c = __cosf(theta), s = __sinf(theta);
        const float v0 = s0 * s0, v1 = s1 * s1;
        const float S00 = c * c * v0 + s * s * v1;
        const float S01 = c * s * (v0 - v1);
        const float S11 = s * s * v0 + c * c * v1;
        const float det = S00 * S11 - S01 * S01;
        const float inv_det = 1.f / det;

        const float coord0 = 2.0f * (float)w / (float)Ww - 1.0f;
        const float coord1 = 2.0f * (float)h / (float)Hh - 1.0f;
        const float x_ndc = coord0 + 2.0f * off0 / (float)Ww - 1.0f / (float)Ww;
        const float y_ndc = coord1 + 2.0f * off1 / (float)Hh - 1.0f / (float)Hh;

        GParam g;
        g.cx = 0.5f * (float)Ww * (x_ndc + 1.0f) - 0.5f;
        g.cy = 0.5f * (float)Hh * (y_ndc + 1.0f) - 0.5f;
        g.ca =  S11 * inv_det;
        g.cb = -S01 * inv_det;
        g.cc =  S00 * inv_det;
        g.r0 = pred[0]; g.r1 = pred[1]; g.r2 = pred[2];
        g_gauss[p] = g;
    }

    // ---- device-wide barrier (unchanged from 12.8us kernel) ----------------
    __threadfence();                     // publish g_gauss GPU-wide
    __syncthreads();                     // whole block done writing
    if (tid == 0) {
        atomicAdd(&g_arrive, 1);
        while (*(volatile int*)&g_arrive < NB) { }
        __threadfence();
        atomicAdd(&g_depart, 1);         // "I will never read g_arrive again"
    }
    __syncthreads();                     // released; all g_gauss visible

    // ---- stage this block's 6x96 gaussian slab into shared -----------------
    // Block pixels span rows [row0, row1] (row1 <= row0+1); every 5x5 window
    // row gh lies in [row0-1, row1+3] subset of [rbase, rbase+5].
    const int rbase = p0 / Ww - 1;
    for (int t = tid; t < 6 * Ww; t += NT) {
        const int gr = rbase + t / Ww;
        if ((unsigned)gr < Hh) {
            const float4* src = reinterpret_cast<const float4*>(&g_gauss[gr * Ww + (t % Ww)]);
            float4* dst = reinterpret_cast<float4*>(&s_g[t]);
            dst[0] = src[0];
            dst[1] = src[1];
        }
    }
    __syncthreads();

    // ---- phase B: rasterize from LDS, 8 lanes per pixel, exact 5x5 window --
    {
        const int pi  = tid >> 3;        // pixel within block [0,64)
        const int sub = tid & 7;
        const int p   = p0 + pi;
        const int px = p % Ww;
        const int py = p / Ww;
        const float fpx = (float)px;
        const float fpy = (float)py;

        float a0 = 0.f, a1 = 0.f, a2 = 0.f;

        #pragma unroll
        for (int j = sub; j < 25; j += 8) {
            const int gh = py - 1 + j / 5;
            const int gw = px - 1 + j % 5;
            if ((unsigned)gh >= Hh || (unsigned)gw >= Ww) continue;
            const GParam g = s_g[(gh - rbase) * Ww + gw];
            const float dx = g.cx - fpx;
            const float dy = g.cy - fpy;
            const float sigma = 0.5f * (g.ca * dx * dx + g.cc * dy * dy) + g.cb * dx * dy;
            if (!(sigma >= 0.f) || sigma > LN255) continue;
            const float alpha = fminf(0.999f, __expf(-sigma));
            a0 += alpha * g.r0;
            a1 += alpha * g.r1;
            a2 += alpha * g.r2;
        }

        #pragma unroll
        for (int m = 1; m < 8; m <<= 1) {
            a0 += __shfl_xor_sync(0xFFFFFFFFu, a0, m);
            a1 += __shfl_xor_sync(0xFFFFFFFFu, a1, m);
            a2 += __shfl_xor_sync(0xFFFFFFFFu, a2, m);
        }

        if (sub == 0)      out[0 * HW + p] = fminf(fmaxf(a0, 0.f), 1.f);
        else if (sub == 1) out[1 * HW + p] = fminf(fmaxf(a1, 0.f), 1.f);
        else if (sub == 2) out[2 * HW + p] = fminf(fmaxf(a2, 0.f), 1.f);
    }

    // ---- reset barrier counters for the next graph replay ------------------
    if (bid == 0 && tid == 0) {
        while (*(volatile int*)&g_depart < NB) { }   // nobody touches g_arrive anymore
        atomicExch(&g_arrive, 0);
        atomicExch(&g_depart, 0);
    }
}

// ---------------------------------------------------------------------------
extern "C" void kernel_launch(void* const* d_in, const int* in_sizes, int n_in,
                              void* d_out, int out_size)
{
    const float* inp    = (const float*)d_in[0];
    const float* w_enc  = (const float*)d_in[1];
    const float* b_enc  = (const float*)d_in[2];
    const float* w_head = (const float*)d_in[3];
    const float* b_head = (const float*)d_in[4];
    float* out = (float*)d_out;

    fused_kernel<<<NB, NT>>>(inp, w_enc, b_enc, w_head, b_head, out);
}